// round 1
// baseline (speedup 1.0000x reference)
#include <cuda_runtime.h>
#include <math.h>

// Problem shape (fixed by the reference)
#define BB 4
#define SQ 4096          // S = maxlength*2
#define DH 1024          // D
// M for the projection GEMM
#define MTOT (BB * SQ)   // 16384

// ---------------- scratch (static __device__, no allocations) ----------------
__device__ float g_Q[(size_t)BB * SQ * DH];
__device__ float g_K[(size_t)BB * SQ * DH];
__device__ float g_V[(size_t)BB * SQ * DH];
__device__ float g_P[(size_t)BB * SQ * SQ];   // logits -> probabilities (256 MB)

// ---------------- tiled SGEMM params ----------------
#define BM 128
#define BN 128
#define BK 8
#define TM 8
#define TN 8
// 256 threads: 16x16 grid of 8x8 micro-tiles

// C[m,n] = sum_k A[m,k] * B[n,k]   (A row-major MxK, B row-major NxK)  — "NT"
// Batched via blockIdx.z with element strides.
__global__ __launch_bounds__(256)
void gemm_nt(const float* __restrict__ A, const float* __restrict__ Bm,
             float* __restrict__ C, int N, int K,
             size_t strA, size_t strB, size_t strC)
{
    __shared__ float As[BK][BM];
    __shared__ float Bs[BK][BN];

    const float* Ab = A + (size_t)blockIdx.z * strA;
    const float* Bb = Bm + (size_t)blockIdx.z * strB;
    float* Cb = C + (size_t)blockIdx.z * strC;

    int tid = threadIdx.x;
    int bm = blockIdx.y * BM;
    int bn = blockIdx.x * BN;

    int lrow = tid >> 1;          // 0..127
    int lk4  = (tid & 1) * 4;     // 0 or 4
    int tx = tid & 15, ty = tid >> 4;

    float acc[TM][TN];
#pragma unroll
    for (int i = 0; i < TM; i++)
#pragma unroll
        for (int j = 0; j < TN; j++) acc[i][j] = 0.f;

    const float* aptr = Ab + (size_t)(bm + lrow) * K + lk4;
    const float* bptr = Bb + (size_t)(bn + lrow) * K + lk4;

    for (int k0 = 0; k0 < K; k0 += BK) {
        float4 a4 = *(const float4*)(aptr + k0);
        float4 b4 = *(const float4*)(bptr + k0);
        As[lk4 + 0][lrow] = a4.x; As[lk4 + 1][lrow] = a4.y;
        As[lk4 + 2][lrow] = a4.z; As[lk4 + 3][lrow] = a4.w;
        Bs[lk4 + 0][lrow] = b4.x; Bs[lk4 + 1][lrow] = b4.y;
        Bs[lk4 + 2][lrow] = b4.z; Bs[lk4 + 3][lrow] = b4.w;
        __syncthreads();
#pragma unroll
        for (int k = 0; k < BK; k++) {
            float ra[TM], rb[TN];
#pragma unroll
            for (int i = 0; i < TM; i++) ra[i] = As[k][ty * TM + i];
#pragma unroll
            for (int j = 0; j < TN; j++) rb[j] = Bs[k][tx * TN + j];
#pragma unroll
            for (int i = 0; i < TM; i++)
#pragma unroll
                for (int j = 0; j < TN; j++)
                    acc[i][j] = fmaf(ra[i], rb[j], acc[i][j]);
        }
        __syncthreads();
    }

#pragma unroll
    for (int i = 0; i < TM; i++) {
        float4 v0 = make_float4(acc[i][0], acc[i][1], acc[i][2], acc[i][3]);
        float4 v1 = make_float4(acc[i][4], acc[i][5], acc[i][6], acc[i][7]);
        size_t base = (size_t)(bm + ty * TM + i) * N + bn + tx * TN;
        *(float4*)(Cb + base)     = v0;
        *(float4*)(Cb + base + 4) = v1;
    }
}

// C[m,n] = sum_k A[m,k] * B[k,n]   (A row-major MxK, B row-major KxN) — "NN"
__global__ __launch_bounds__(256)
void gemm_nn(const float* __restrict__ A, const float* __restrict__ Bm,
             float* __restrict__ C, int N, int K,
             size_t strA, size_t strB, size_t strC)
{
    __shared__ float As[BK][BM];
    __shared__ float Bs[BK][BN];

    const float* Ab = A + (size_t)blockIdx.z * strA;
    const float* Bb = Bm + (size_t)blockIdx.z * strB;
    float* Cb = C + (size_t)blockIdx.z * strC;

    int tid = threadIdx.x;
    int bm = blockIdx.y * BM;
    int bn = blockIdx.x * BN;

    int lrow = tid >> 1;          // A: 0..127
    int lk4  = (tid & 1) * 4;
    int bk   = tid >> 5;          // B: k row 0..7
    int bn4  = (tid & 31) * 4;    // B: col 0..124
    int tx = tid & 15, ty = tid >> 4;

    float acc[TM][TN];
#pragma unroll
    for (int i = 0; i < TM; i++)
#pragma unroll
        for (int j = 0; j < TN; j++) acc[i][j] = 0.f;

    const float* aptr = Ab + (size_t)(bm + lrow) * K + lk4;

    for (int k0 = 0; k0 < K; k0 += BK) {
        float4 a4 = *(const float4*)(aptr + k0);
        As[lk4 + 0][lrow] = a4.x; As[lk4 + 1][lrow] = a4.y;
        As[lk4 + 2][lrow] = a4.z; As[lk4 + 3][lrow] = a4.w;
        float4 b4 = *(const float4*)(Bb + (size_t)(k0 + bk) * N + bn + bn4);
        *(float4*)&Bs[bk][bn4] = b4;
        __syncthreads();
#pragma unroll
        for (int k = 0; k < BK; k++) {
            float ra[TM], rb[TN];
#pragma unroll
            for (int i = 0; i < TM; i++) ra[i] = As[k][ty * TM + i];
#pragma unroll
            for (int j = 0; j < TN; j++) rb[j] = Bs[k][tx * TN + j];
#pragma unroll
            for (int i = 0; i < TM; i++)
#pragma unroll
                for (int j = 0; j < TN; j++)
                    acc[i][j] = fmaf(ra[i], rb[j], acc[i][j]);
        }
        __syncthreads();
    }

#pragma unroll
    for (int i = 0; i < TM; i++) {
        float4 v0 = make_float4(acc[i][0], acc[i][1], acc[i][2], acc[i][3]);
        float4 v1 = make_float4(acc[i][4], acc[i][5], acc[i][6], acc[i][7]);
        size_t base = (size_t)(bm + ty * TM + i) * N + bn + tx * TN;
        *(float4*)(Cb + base)     = v0;
        *(float4*)(Cb + base + 4) = v1;
    }
}

// Masked softmax over each logits row; masked tail written as exact 0.
__global__ __launch_bounds__(256)
void softmax_mask(float* __restrict__ P, const int* __restrict__ length)
{
    int row = blockIdx.x;            // 0 .. BB*SQ-1
    int b = row >> 12;               // row / SQ
    float* p = P + (size_t)row * SQ;
    int valid = length[b] * 2;       // key-padding boundary (<= SQ)

    __shared__ float red[256];
    int t = threadIdx.x;

    // ---- max over valid ----
    float m = -INFINITY;
    for (int k = t; k < valid; k += 256) m = fmaxf(m, p[k]);
    red[t] = m;
    __syncthreads();
    for (int s = 128; s > 0; s >>= 1) {
        if (t < s) red[t] = fmaxf(red[t], red[t + s]);
        __syncthreads();
    }
    float mx = red[0];
    __syncthreads();

    // ---- sum of exp ----
    float s = 0.f;
    for (int k = t; k < valid; k += 256) s += expf(p[k] - mx);
    red[t] = s;
    __syncthreads();
    for (int q = 128; q > 0; q >>= 1) {
        if (t < q) red[t] += red[t + q];
        __syncthreads();
    }
    float inv = 1.0f / red[0];

    // ---- write probs, zero the masked tail ----
    for (int k = t; k < valid; k += 256) p[k] = expf(p[k] - mx) * inv;
    for (int k = valid + t; k < SQ; k += 256) p[k] = 0.f;
}

extern "C" void kernel_launch(void* const* d_in, const int* in_sizes, int n_in,
                              void* d_out, int out_size)
{
    const float* x   = (const float*)d_in[0];   // [B,S,D]
    const int*   len = (const int*)d_in[1];     // [B]
    const float* Wq  = (const float*)d_in[2];   // [D,D]
    const float* Wk  = (const float*)d_in[3];
    const float* Wv  = (const float*)d_in[4];
    float* out = (float*)d_out;                  // [B,S,D]

    float *gq, *gk, *gv, *gp;
    cudaGetSymbolAddress((void**)&gq, g_Q);
    cudaGetSymbolAddress((void**)&gk, g_K);
    cudaGetSymbolAddress((void**)&gv, g_V);
    cudaGetSymbolAddress((void**)&gp, g_P);

    dim3 blk(256);

    // 1) Projections: Y[m,n] = sum_d X[m,d] * W[n,d]  (NT), M=16384, N=K=1024
    {
        dim3 grid(DH / BN, MTOT / BM, 1);
        gemm_nt<<<grid, blk>>>(x, Wq, gq, DH, DH, 0, 0, 0);
        gemm_nt<<<grid, blk>>>(x, Wk, gk, DH, DH, 0, 0, 0);
        gemm_nt<<<grid, blk>>>(x, Wv, gv, DH, DH, 0, 0, 0);
    }

    // 2) Logits: P[b,q,k] = Q[b,q,:] . K[b,k,:]  (batched NT), M=N=4096, K=1024
    {
        dim3 grid(SQ / BN, SQ / BM, BB);
        gemm_nt<<<grid, blk>>>(gq, gk, gp, SQ, DH,
                               (size_t)SQ * DH, (size_t)SQ * DH, (size_t)SQ * SQ);
    }

    // 3) Masked softmax per row
    softmax_mask<<<BB * SQ, blk>>>(gp, len);

    // 4) Out: O[b,q,d] = sum_k P[b,q,k] * V[b,k,d]  (batched NN), M=4096, N=1024, K=4096
    {
        dim3 grid(DH / BN, SQ / BM, BB);
        gemm_nn<<<grid, blk>>>(gp, gv, out, DH, SQ,
                               (size_t)SQ * SQ, (size_t)SQ * DH, (size_t)SQ * DH);
    }
}

// round 6
// speedup vs baseline: 2.5875x; 2.5875x over previous
#include <cuda_runtime.h>
#include <cuda_bf16.h>
#include <cstdint>
#include <math.h>

#define BB 4
#define SQ 4096
#define DH 1024
#define MTOT (BB * SQ)   // 16384

typedef __nv_bfloat16  bf16;
typedef __nv_bfloat162 bf162;

// ---------------- scratch planes (hi/lo bf16 split) ----------------
__device__ bf16 g_Xh[(size_t)MTOT * DH], g_Xl[(size_t)MTOT * DH];
__device__ bf16 g_Wqh[(size_t)DH * DH], g_Wql[(size_t)DH * DH];
__device__ bf16 g_Wkh[(size_t)DH * DH], g_Wkl[(size_t)DH * DH];
__device__ bf16 g_Wvh[(size_t)DH * DH], g_Wvl[(size_t)DH * DH];
__device__ bf16 g_Qh[(size_t)MTOT * DH], g_Ql[(size_t)MTOT * DH];
__device__ bf16 g_Kh[(size_t)MTOT * DH], g_Kl[(size_t)MTOT * DH];
__device__ float g_V[(size_t)MTOT * DH];
__device__ bf16 g_Vth[(size_t)MTOT * DH], g_Vtl[(size_t)MTOT * DH];
__device__ float g_P[(size_t)BB * SQ * SQ];
__device__ bf16 g_Ph[(size_t)BB * SQ * SQ], g_Pl[(size_t)BB * SQ * SQ];

// ---------------- PTX helpers (sm_80-era; legal on .target sm_103) ----------------
__device__ __forceinline__ uint32_t smem_u32(const void* p) {
    uint32_t a;
    asm("{ .reg .u64 t; cvta.to.shared.u64 t, %1; cvt.u32.u64 %0, t; }" : "=r"(a) : "l"(p));
    return a;
}
__device__ __forceinline__ void cp16(uint32_t dst, const void* src) {
    asm volatile("cp.async.cg.shared.global [%0], [%1], 16;" :: "r"(dst), "l"(src));
}
#define CP_COMMIT() asm volatile("cp.async.commit_group;" ::: "memory")
#define CP_WAIT1()  asm volatile("cp.async.wait_group 1;" ::: "memory")

__device__ __forceinline__ void ldm4(uint32_t* r, uint32_t a) {
    asm volatile("ldmatrix.sync.aligned.m8n8.x4.shared.b16 {%0,%1,%2,%3}, [%4];"
                 : "=r"(r[0]), "=r"(r[1]), "=r"(r[2]), "=r"(r[3]) : "r"(a));
}
__device__ __forceinline__ void ldm2(uint32_t* r, uint32_t a) {
    asm volatile("ldmatrix.sync.aligned.m8n8.x2.shared.b16 {%0,%1}, [%2];"
                 : "=r"(r[0]), "=r"(r[1]) : "r"(a));
}
__device__ __forceinline__ void mma16816(float* d, const uint32_t* a, const uint32_t* b) {
    asm volatile("mma.sync.aligned.m16n8k16.row.col.f32.bf16.bf16.f32 "
                 "{%0,%1,%2,%3}, {%4,%5,%6,%7}, {%8,%9}, {%0,%1,%2,%3};"
                 : "+f"(d[0]), "+f"(d[1]), "+f"(d[2]), "+f"(d[3])
                 : "r"(a[0]), "r"(a[1]), "r"(a[2]), "r"(a[3]), "r"(b[0]), "r"(b[1]));
}

// ---------------- GEMM config ----------------
// C[m,n] = sum_k A[m,k]*B[n,k], both operands bf16 hi/lo planes, K-major.
// Tile 128x128x32, 256 threads (8 warps, 2x4), warp tile 64x32.
#define STAGES 3
#define ROWB 80              // padded smem row: 32 bf16 = 64B + 16B pad
#define TILEB (128 * ROWB)   // 10240
#define STAGEB (4 * TILEB)   // 40960: [Ah | Al | Bh | Bl]
#define SMEM_GEMM (STAGES * STAGEB)

__global__ void __launch_bounds__(256, 1) gemm_bf16_3p(
    const bf16* __restrict__ Ah, const bf16* __restrict__ Al,
    const bf16* __restrict__ Bh, const bf16* __restrict__ Bl,
    float* __restrict__ Cf, bf16* __restrict__ Ch, bf16* __restrict__ Cl,
    int K, int ldc, size_t sA, size_t sB, size_t sC)
{
    extern __shared__ char smem[];
    const uint32_t sb = smem_u32(smem);
    const int tid = threadIdx.x;
    const int wid = tid >> 5, lane = tid & 31;
    const int wm = wid & 1, wn = wid >> 1;     // 2 x 4 warps

    const size_t aoff = (size_t)blockIdx.z * sA + (size_t)(blockIdx.y * 128) * K;
    const size_t boff = (size_t)blockIdx.z * sB + (size_t)(blockIdx.x * 128) * K;
    const bf16* Abh = Ah + aoff;
    const bf16* Abl = Al + aoff;
    const bf16* Bbh = Bh + boff;
    const bf16* Bbl = Bl + boff;

    float acc[4][4][4];
#pragma unroll
    for (int i = 0; i < 4; i++)
#pragma unroll
        for (int j = 0; j < 4; j++)
#pragma unroll
            for (int q = 0; q < 4; q++) acc[i][j][q] = 0.f;

    const int nch = K / 32;

    // per-thread load indices: 2 cp.async per tile, 4 tiles
    const int r0 = tid >> 2;             // rows 0..63
    const int c0 = tid & 3;              // 16B chunk 0..3

    // ldmatrix source coords
    const int rA = lane & 15, cA = (lane >> 4) * 8;
    const int rr = lane & 15;
    const int rB = rr & 7, cB = (rr >> 3) * 8;

#define LOAD_CHUNK(stg, ko)                                                     \
    do {                                                                        \
        uint32_t dst0 = sb + (stg) * STAGEB;                                    \
        int kk = (ko) * 32;                                                     \
        const bf16* s0 = Abh + (size_t)r0 * K + kk + c0 * 8;                    \
        const bf16* s1 = Abl + (size_t)r0 * K + kk + c0 * 8;                    \
        const bf16* s2 = Bbh + (size_t)r0 * K + kk + c0 * 8;                    \
        const bf16* s3 = Bbl + (size_t)r0 * K + kk + c0 * 8;                    \
        uint32_t d = dst0 + r0 * ROWB + c0 * 16;                                \
        cp16(d,             s0); cp16(d + TILEB,     s1);                       \
        cp16(d + 2 * TILEB, s2); cp16(d + 3 * TILEB, s3);                       \
        const size_t k64 = (size_t)64 * K;                                      \
        uint32_t d2 = d + 64 * ROWB;                                            \
        cp16(d2,             s0 + k64); cp16(d2 + TILEB,     s1 + k64);         \
        cp16(d2 + 2 * TILEB, s2 + k64); cp16(d2 + 3 * TILEB, s3 + k64);         \
    } while (0)

    // prologue: stages-1 chunks in flight
#pragma unroll
    for (int s = 0; s < STAGES - 1; s++) {
        if (s < nch) LOAD_CHUNK(s, s);
        CP_COMMIT();
    }

    for (int ch = 0; ch < nch; ch++) {
        CP_WAIT1();
        __syncthreads();

        const uint32_t st = sb + (ch % STAGES) * STAGEB;
        const uint32_t pAh = st + (wm * 64 + rA) * ROWB + cA * 2;
        const uint32_t pAl = pAh + TILEB;
        const uint32_t pBh = st + 2 * TILEB + (wn * 32 + rB) * ROWB + cB * 2;
        const uint32_t pBl = pBh + TILEB;

#pragma unroll
        for (int ks = 0; ks < 2; ks++) {
            const uint32_t kofs = ks * 32;   // 16 bf16 = 32 bytes
            uint32_t ah[4][4], al[4][4], bh[4][2], bl[4][2];
#pragma unroll
            for (int mf = 0; mf < 4; mf++) {
                ldm4(ah[mf], pAh + mf * (16 * ROWB) + kofs);
                ldm4(al[mf], pAl + mf * (16 * ROWB) + kofs);
            }
#pragma unroll
            for (int nf = 0; nf < 4; nf++) {
                ldm2(bh[nf], pBh + nf * (8 * ROWB) + kofs);
                ldm2(bl[nf], pBl + nf * (8 * ROWB) + kofs);
            }
#pragma unroll
            for (int mf = 0; mf < 4; mf++)
#pragma unroll
                for (int nf = 0; nf < 4; nf++) {
                    mma16816(acc[mf][nf], ah[mf], bh[nf]);   // hi*hi
                    mma16816(acc[mf][nf], ah[mf], bl[nf]);   // hi*lo
                    mma16816(acc[mf][nf], al[mf], bh[nf]);   // lo*hi
                }
        }
        __syncthreads();

        int nx = ch + STAGES - 1;
        if (nx < nch) LOAD_CHUNK(nx % STAGES, nx);
        CP_COMMIT();
    }

    // ---------------- epilogue ----------------
    const size_t coff = (size_t)blockIdx.z * sC;
#pragma unroll
    for (int mf = 0; mf < 4; mf++) {
#pragma unroll
        for (int nf = 0; nf < 4; nf++) {
            int row = blockIdx.y * 128 + wm * 64 + mf * 16 + (lane >> 2);
            int col = blockIdx.x * 128 + wn * 32 + nf * 8 + (lane & 3) * 2;
            float* a4 = acc[mf][nf];
            if (Cf) {
                *(float2*)(Cf + coff + (size_t)row * ldc + col)       = make_float2(a4[0], a4[1]);
                *(float2*)(Cf + coff + (size_t)(row + 8) * ldc + col) = make_float2(a4[2], a4[3]);
            }
            if (Ch) {
                bf16 h0 = __float2bfloat16_rn(a4[0]);
                bf16 h1 = __float2bfloat16_rn(a4[1]);
                bf16 h2 = __float2bfloat16_rn(a4[2]);
                bf16 h3 = __float2bfloat16_rn(a4[3]);
                bf16 l0 = __float2bfloat16_rn(a4[0] - __bfloat162float(h0));
                bf16 l1 = __float2bfloat16_rn(a4[1] - __bfloat162float(h1));
                bf16 l2 = __float2bfloat16_rn(a4[2] - __bfloat162float(h2));
                bf16 l3 = __float2bfloat16_rn(a4[3] - __bfloat162float(h3));
                size_t o0 = coff + (size_t)row * ldc + col;
                size_t o1 = coff + (size_t)(row + 8) * ldc + col;
                *(bf162*)(Ch + o0) = bf162(h0, h1);
                *(bf162*)(Ch + o1) = bf162(h2, h3);
                *(bf162*)(Cl + o0) = bf162(l0, l1);
                *(bf162*)(Cl + o1) = bf162(l2, l3);
            }
        }
    }
}

// ---------------- elementwise fp32 -> hi/lo bf16 split ----------------
__global__ __launch_bounds__(256)
void split_f32(const float4* __restrict__ src, bf162* __restrict__ h,
               bf162* __restrict__ l, size_t n4)
{
    size_t i = (size_t)blockIdx.x * blockDim.x + threadIdx.x;
    if (i >= n4) return;
    float4 v = src[i];
    bf16 h0 = __float2bfloat16_rn(v.x), h1 = __float2bfloat16_rn(v.y);
    bf16 h2 = __float2bfloat16_rn(v.z), h3 = __float2bfloat16_rn(v.w);
    h[2 * i]     = bf162(h0, h1);
    h[2 * i + 1] = bf162(h2, h3);
    l[2 * i]     = bf162(__float2bfloat16_rn(v.x - __bfloat162float(h0)),
                         __float2bfloat16_rn(v.y - __bfloat162float(h1)));
    l[2 * i + 1] = bf162(__float2bfloat16_rn(v.z - __bfloat162float(h2)),
                         __float2bfloat16_rn(v.w - __bfloat162float(h3)));
}

// ---------------- V transpose + split: Vt[b][d][s] ----------------
__global__ __launch_bounds__(256)
void transpose_split(const float* __restrict__ V, bf16* __restrict__ Th,
                     bf16* __restrict__ Tl)
{
    __shared__ float t[32][33];
    int b = blockIdx.z;
    int s0 = blockIdx.x * 32, d0 = blockIdx.y * 32;
    const float* Vb = V + (size_t)b * SQ * DH;
    int x = threadIdx.x, y = threadIdx.y;
#pragma unroll
    for (int i = 0; i < 32; i += 8)
        t[y + i][x] = Vb[(size_t)(s0 + y + i) * DH + d0 + x];
    __syncthreads();
    bf16* Thb = Th + (size_t)b * DH * SQ;
    bf16* Tlb = Tl + (size_t)b * DH * SQ;
#pragma unroll
    for (int i = 0; i < 32; i += 8) {
        float v = t[x][y + i];
        bf16 hv = __float2bfloat16_rn(v);
        size_t o = (size_t)(d0 + y + i) * SQ + s0 + x;
        Thb[o] = hv;
        Tlb[o] = __float2bfloat16_rn(v - __bfloat162float(hv));
    }
}

// ---------------- masked softmax: fp32 logits -> hi/lo bf16 probs ----------------
__global__ __launch_bounds__(256)
void softmax_mask(const float* __restrict__ P, bf16* __restrict__ Ph,
                  bf16* __restrict__ Pl, const int* __restrict__ length)
{
    int row = blockIdx.x;
    int b = row >> 12;
    const float4* p4 = (const float4*)(P + (size_t)row * SQ);
    int valid = length[b] * 2;
    int t = threadIdx.x;

    float4 v[4];
    float e[16];
#pragma unroll
    for (int i = 0; i < 4; i++) v[i] = p4[i * 256 + t];

    // max over valid
    float m = -INFINITY;
#pragma unroll
    for (int i = 0; i < 4; i++) {
        int k = (i * 256 + t) * 4;
        if (k + 0 < valid) m = fmaxf(m, v[i].x);
        if (k + 1 < valid) m = fmaxf(m, v[i].y);
        if (k + 2 < valid) m = fmaxf(m, v[i].z);
        if (k + 3 < valid) m = fmaxf(m, v[i].w);
    }
#pragma unroll
    for (int o = 16; o > 0; o >>= 1) m = fmaxf(m, __shfl_xor_sync(~0u, m, o));
    __shared__ float red[8];
    if ((t & 31) == 0) red[t >> 5] = m;
    __syncthreads();
    if (t < 8) {
        float q = red[t];
#pragma unroll
        for (int o = 4; o > 0; o >>= 1) q = fmaxf(q, __shfl_xor_sync(0xFFu, q, o));
        red[t] = q;
    }
    __syncthreads();
    float mx = red[0];
    __syncthreads();

    // exp + sum
    float s = 0.f;
#pragma unroll
    for (int i = 0; i < 4; i++) {
        int k = (i * 256 + t) * 4;
        e[4 * i + 0] = (k + 0 < valid) ? __expf(v[i].x - mx) : 0.f;
        e[4 * i + 1] = (k + 1 < valid) ? __expf(v[i].y - mx) : 0.f;
        e[4 * i + 2] = (k + 2 < valid) ? __expf(v[i].z - mx) : 0.f;
        e[4 * i + 3] = (k + 3 < valid) ? __expf(v[i].w - mx) : 0.f;
        s += e[4 * i] + e[4 * i + 1] + e[4 * i + 2] + e[4 * i + 3];
    }
#pragma unroll
    for (int o = 16; o > 0; o >>= 1) s += __shfl_xor_sync(~0u, s, o);
    __shared__ float red2[8];
    if ((t & 31) == 0) red2[t >> 5] = s;
    __syncthreads();
    if (t < 8) {
        float q = red2[t];
#pragma unroll
        for (int o = 4; o > 0; o >>= 1) q += __shfl_xor_sync(0xFFu, q, o);
        red2[t] = q;
    }
    __syncthreads();
    float inv = 1.0f / red2[0];

    bf162* ph = (bf162*)(Ph + (size_t)row * SQ);
    bf162* pl = (bf162*)(Pl + (size_t)row * SQ);
#pragma unroll
    for (int i = 0; i < 4; i++) {
#pragma unroll
        for (int j = 0; j < 2; j++) {
            float a = e[4 * i + 2 * j] * inv, c = e[4 * i + 2 * j + 1] * inv;
            bf16 ha = __float2bfloat16_rn(a), hc = __float2bfloat16_rn(c);
            bf16 la = __float2bfloat16_rn(a - __bfloat162float(ha));
            bf16 lc = __float2bfloat16_rn(c - __bfloat162float(hc));
            int o = (i * 256 + t) * 2 + j;
            ph[o] = bf162(ha, hc);
            pl[o] = bf162(la, lc);
        }
    }
}

// ---------------- host launcher ----------------
extern "C" void kernel_launch(void* const* d_in, const int* in_sizes, int n_in,
                              void* d_out, int out_size)
{
    const float* x   = (const float*)d_in[0];
    const int*   len = (const int*)d_in[1];
    const float* Wq  = (const float*)d_in[2];
    const float* Wk  = (const float*)d_in[3];
    const float* Wv  = (const float*)d_in[4];
    float* out = (float*)d_out;

    bf16 *xh, *xl, *wqh, *wql, *wkh, *wkl, *wvh, *wvl;
    bf16 *qh, *ql, *kh, *kl, *vth, *vtl, *ph, *pl;
    float *gv, *gp;
    cudaGetSymbolAddress((void**)&xh, g_Xh);   cudaGetSymbolAddress((void**)&xl, g_Xl);
    cudaGetSymbolAddress((void**)&wqh, g_Wqh); cudaGetSymbolAddress((void**)&wql, g_Wql);
    cudaGetSymbolAddress((void**)&wkh, g_Wkh); cudaGetSymbolAddress((void**)&wkl, g_Wkl);
    cudaGetSymbolAddress((void**)&wvh, g_Wvh); cudaGetSymbolAddress((void**)&wvl, g_Wvl);
    cudaGetSymbolAddress((void**)&qh, g_Qh);   cudaGetSymbolAddress((void**)&ql, g_Ql);
    cudaGetSymbolAddress((void**)&kh, g_Kh);   cudaGetSymbolAddress((void**)&kl, g_Kl);
    cudaGetSymbolAddress((void**)&gv, g_V);
    cudaGetSymbolAddress((void**)&vth, g_Vth); cudaGetSymbolAddress((void**)&vtl, g_Vtl);
    cudaGetSymbolAddress((void**)&gp, g_P);
    cudaGetSymbolAddress((void**)&ph, g_Ph);   cudaGetSymbolAddress((void**)&pl, g_Pl);

    cudaFuncSetAttribute(gemm_bf16_3p, cudaFuncAttributeMaxDynamicSharedMemorySize, SMEM_GEMM);

    // 0) split inputs and weights into bf16 hi/lo planes
    {
        size_t n4 = (size_t)MTOT * DH / 4;
        split_f32<<<(unsigned)((n4 + 255) / 256), 256>>>((const float4*)x, (bf162*)xh, (bf162*)xl, n4);
        size_t w4 = (size_t)DH * DH / 4;
        unsigned wg = (unsigned)((w4 + 255) / 256);
        split_f32<<<wg, 256>>>((const float4*)Wq, (bf162*)wqh, (bf162*)wql, w4);
        split_f32<<<wg, 256>>>((const float4*)Wk, (bf162*)wkh, (bf162*)wkl, w4);
        split_f32<<<wg, 256>>>((const float4*)Wv, (bf162*)wvh, (bf162*)wvl, w4);
    }

    // 1) projections: M=16384, N=1024, K=1024
    {
        dim3 g(DH / 128, MTOT / 128, 1), blk(256);
        gemm_bf16_3p<<<g, blk, SMEM_GEMM>>>(xh, xl, wqh, wql, nullptr, qh, ql, DH, DH, 0, 0, 0);
        gemm_bf16_3p<<<g, blk, SMEM_GEMM>>>(xh, xl, wkh, wkl, nullptr, kh, kl, DH, DH, 0, 0, 0);
        gemm_bf16_3p<<<g, blk, SMEM_GEMM>>>(xh, xl, wvh, wvl, gv, nullptr, nullptr, DH, DH, 0, 0, 0);
    }

    // 2) logits: batched M=N=4096, K=1024 -> fp32 P
    {
        dim3 g(SQ / 128, SQ / 128, BB), blk(256);
        gemm_bf16_3p<<<g, blk, SMEM_GEMM>>>(qh, ql, kh, kl, gp, nullptr, nullptr, DH, SQ,
                                            (size_t)SQ * DH, (size_t)SQ * DH, (size_t)SQ * SQ);
    }

    // 3) V -> Vt hi/lo planes
    {
        dim3 g(SQ / 32, DH / 32, BB);
        transpose_split<<<g, dim3(32, 8)>>>(gv, vth, vtl);
    }

    // 4) masked softmax -> P hi/lo planes
    softmax_mask<<<BB * SQ, 256>>>(gp, ph, pl, len);

    // 5) out = P @ V: batched M=4096, N=1024, K=4096
    {
        dim3 g(DH / 128, SQ / 128, BB), blk(256);
        gemm_bf16_3p<<<g, blk, SMEM_GEMM>>>(ph, pl, vth, vtl, out, nullptr, nullptr, SQ, DH,
                                            (size_t)SQ * SQ, (size_t)DH * SQ, (size_t)SQ * DH);
    }
}